// round 14
// baseline (speedup 1.0000x reference)
#include <cuda_runtime.h>
#include <cuda_bf16.h>
#include <cuda_fp16.h>
#include <math.h>
#include <stdint.h>

#define BATCH 4
#define CH    256
#define HW    4096
#define NSPLIT 64            // 32 i-tiles * 2 m-warps (split = i >> 6)
#define NCHUNK 8             // K chunks of 32 channels
#define STAGEB 32768         // A(16K: hi8|lo8) | B(16K: hi8|lo8)
#define NSTAGE 3
#define SMEM_REQ (NSTAGE*STAGEB + 1024 + 128)

// staging: per (b, cc, ib128): 16KB block = [hi 8KB | lo 8KB], rows of 64B slot-swizzled
__device__ __nv_bfloat16 g_A[BATCH*NCHUNK*HW*64];    // feat1 (i rows)
__device__ __nv_bfloat16 g_B[BATCH*NCHUNK*HW*64];    // feat2 (j rows)

__device__ __half g_e[(size_t)BATCH*HW*HW];          // exp(x - m_split), fp16
__device__ float g_pm[NSPLIT*BATCH*HW];
__device__ float g_ps[NSPLIT*BATCH*HW];
__device__ float g_sc[NSPLIT*BATCH*HW];              // exp(m_split-m)*inv

// ------------------------------------------------------------------ helpers
static __device__ __forceinline__ uint32_t smem_u32(const void* p){
    uint32_t a;
    asm("{ .reg .u64 t; cvta.to.shared.u64 t, %1; cvt.u32.u64 %0, t; }" : "=r"(a) : "l"(p));
    return a;
}
static __device__ __forceinline__ uint32_t h2_bits(__half2 h){
    uint32_t u;
    *(__half2*)&u = h;
    return u;
}
static __device__ __forceinline__ void mbar_init(uint32_t a, uint32_t c){
    asm volatile("mbarrier.init.shared.b64 [%0], %1;" :: "r"(a), "r"(c) : "memory");
}
static __device__ __forceinline__ void mbar_expect(uint32_t a, uint32_t tx){
    asm volatile("mbarrier.arrive.expect_tx.shared.b64 _, [%0], %1;" :: "r"(a), "r"(tx) : "memory");
}
static __device__ __forceinline__ void mbar_arrive(uint32_t a){
    asm volatile("mbarrier.arrive.shared.b64 _, [%0];" :: "r"(a) : "memory");
}
static __device__ __forceinline__ void mbar_wait(uint32_t a, uint32_t par){
    asm volatile("{\n\t.reg .pred P;\n\t"
                 "WL_%=:\n\t"
                 "mbarrier.try_wait.parity.acquire.cta.shared::cta.b64 P, [%0], %1, 0x989680;\n\t"
                 "@P bra WD_%=;\n\t"
                 "bra WL_%=;\n\t"
                 "WD_%=:\n\t}" :: "r"(a), "r"(par) : "memory");
}
static __device__ __forceinline__ void bulk_g2s(uint32_t dst, const void* src,
                                                uint32_t bytes, uint32_t mbar){
    asm volatile("cp.async.bulk.shared::cluster.global.mbarrier::complete_tx::bytes "
                 "[%0], [%1], %2, [%3];"
                 :: "r"(dst), "l"(src), "r"(bytes), "r"(mbar) : "memory");
}

#define LDSM4(r, addr) \
    asm volatile("ldmatrix.sync.aligned.m8n8.x4.shared.b16 {%0,%1,%2,%3}, [%4];" \
        : "=r"((r)[0]), "=r"((r)[1]), "=r"((r)[2]), "=r"((r)[3]) : "r"(addr))

#define MMA(d, a, bb) \
    asm volatile("mma.sync.aligned.m16n8k16.row.col.f32.bf16.bf16.f32 " \
        "{%0,%1,%2,%3},{%4,%5,%6,%7},{%8,%9},{%0,%1,%2,%3};" \
        : "+f"((d)[0]), "+f"((d)[1]), "+f"((d)[2]), "+f"((d)[3]) \
        : "r"((a)[0]), "r"((a)[1]), "r"((a)[2]), "r"((a)[3]), "r"((bb)[0]), "r"((bb)[1]))

// ------------------------------------------------------------------ pre-pass
__global__ __launch_bounds__(256) void split_prep(const float* __restrict__ f1,
                                                  const float* __restrict__ f2)
{
    __shared__ float s[32][129];
    const int bid = blockIdx.x;
    const int ib  = bid & 31;
    const int cc  = (bid >> 5) & 7;
    const int b   = (bid >> 8) & 3;
    const int arr = bid >> 10;
    const float* in = arr ? f2 : f1;
    __nv_bfloat16* o = arr ? g_B : g_A;
    const int t = threadIdx.x;

#pragma unroll
    for (int k = 0; k < 4; k++) {
        const int lin = k * 256 + t;
        const int c   = lin >> 5;
        const int x4  = lin & 31;
        const float4 v = *(const float4*)(in + ((size_t)(b*CH + cc*32 + c))*HW + ib*128 + x4*4);
        s[c][x4*4+0] = v.x; s[c][x4*4+1] = v.y; s[c][x4*4+2] = v.z; s[c][x4*4+3] = v.w;
    }
    __syncthreads();

    const int slot = t & 3;
    const size_t blk = (((size_t)(b*NCHUNK + cc))*32 + ib) * 16384;
#pragma unroll
    for (int rr = 0; rr < 2; rr++) {
        const int row = rr * 64 + (t >> 2);
        const uint32_t byte = (uint32_t)(row * 64) +
                              ((uint32_t)(slot << 4) ^ (uint32_t)(((row >> 1) & 3) << 4));
        uint32_t hp[4], lp[4];
#pragma unroll
        for (int u = 0; u < 4; u++) {
            const int c = slot*8 + u*2;
            const float v0 = s[c][row], v1 = s[c+1][row];
            const __nv_bfloat16 h0 = __float2bfloat16(v0);
            const __nv_bfloat16 h1 = __float2bfloat16(v1);
            const __nv_bfloat16 l0 = __float2bfloat16(v0 - __bfloat162float(h0));
            const __nv_bfloat16 l1 = __float2bfloat16(v1 - __bfloat162float(h1));
            hp[u] = ((uint32_t)__bfloat16_as_ushort(h1) << 16) | __bfloat16_as_ushort(h0);
            lp[u] = ((uint32_t)__bfloat16_as_ushort(l1) << 16) | __bfloat16_as_ushort(l0);
        }
        *(uint4*)((char*)o + blk        + byte) = make_uint4(hp[0], hp[1], hp[2], hp[3]);
        *(uint4*)((char*)o + blk + 8192 + byte) = make_uint4(lp[0], lp[1], lp[2], lp[3]);
    }
}

// ------------------------------------------------------------------ GEMM
// C[i,j] tile 128x128, 128 threads, bf16-3x, 3-stage pipeline, 2 CTAs/SM.
// Epilogue: exp -> smem (swizzled, AFTER barrier) -> coalesced STG.128.
__global__ __launch_bounds__(128, 2) void corr_mma()
{
    extern __shared__ char dsm[];
    uint32_t base = smem_u32(dsm);
    base = (base + 1023) & ~1023u;
    const uint32_t mbF = base + NSTAGE * STAGEB;
    const uint32_t mbE = mbF + 24;

    const int tid  = threadIdx.x;
    const int lane = tid & 31;
    const int wid  = tid >> 5;
    const int wm   = wid >> 1;
    const int wn   = wid & 1;
    const int jt = blockIdx.x, it = blockIdx.y, b = blockIdx.z;

    if (tid == 0) {
#pragma unroll
        for (int s = 0; s < NSTAGE; s++) { mbar_init(mbF + 8*s, 1); mbar_init(mbE + 8*s, 4); }
        asm volatile("fence.proxy.async.shared::cta;" ::: "memory");
    }
    __syncthreads();

    #define ISSUE(c, s) do { \
        const size_t offA = (((size_t)(b*NCHUNK + (c)))*32 + it) * 16384; \
        const size_t offB = (((size_t)(b*NCHUNK + (c)))*32 + jt) * 16384; \
        mbar_expect(mbF + 8*(s), STAGEB); \
        bulk_g2s(base + (s)*STAGEB +     0, (const char*)g_A + offA, 16384, mbF + 8*(s)); \
        bulk_g2s(base + (s)*STAGEB + 16384, (const char*)g_B + offB, 16384, mbF + 8*(s)); \
    } while (0)

    if (tid == 0) { ISSUE(0,0); ISSUE(1,1); ISSUE(2,2); }

    float acc[4][8][4];
#pragma unroll
    for (int mt = 0; mt < 4; mt++)
#pragma unroll
        for (int nt = 0; nt < 8; nt++)
#pragma unroll
            for (int e = 0; e < 4; e++) acc[mt][nt][e] = 0.f;

    const int rA  = lane & 15;
    const int khA = (lane & 16) ? 16 : 0;
    const int rB  = (lane & 7) + ((lane & 16) ? 8 : 0);
    const int khB = (lane & 8)  ? 16 : 0;
    const uint32_t swA = (uint32_t)(((rA >> 1) & 3) << 4);
    const uint32_t swB = (uint32_t)(((rB >> 1) & 3) << 4);
    const uint32_t rowAoff = (uint32_t)((wm*64 + rA) * 64);
    const uint32_t rowBoff = (uint32_t)(16384 + (wn*64 + rB) * 64);

    for (int c = 0; c < NCHUNK; c++) {
        const int s = c % NSTAGE;
        const uint32_t par = (uint32_t)((c / NSTAGE) & 1);
        mbar_wait(mbF + 8*s, par);

        const uint32_t aAh = base + s*STAGEB + rowAoff;
        const uint32_t aAl = aAh + 8192;
        const uint32_t aBh = base + s*STAGEB + rowBoff;
        const uint32_t aBl = aBh + 8192;

#pragma unroll
        for (int kk = 0; kk < 2; kk++) {
            const uint32_t colA = ((uint32_t)(kk*32 + khA)) ^ swA;
            const uint32_t colB = ((uint32_t)(kk*32 + khB)) ^ swB;
            uint32_t ah[4][4], al[4][4], bh[4][4], bl[4][4];
#pragma unroll
            for (int mt = 0; mt < 4; mt++) {
                LDSM4(ah[mt], aAh + mt*1024 + colA);
                LDSM4(al[mt], aAl + mt*1024 + colA);
            }
#pragma unroll
            for (int np = 0; np < 4; np++) {
                LDSM4(bh[np], aBh + np*1024 + colB);
                LDSM4(bl[np], aBl + np*1024 + colB);
            }
#pragma unroll
            for (int mt = 0; mt < 4; mt++)
#pragma unroll
                for (int nt = 0; nt < 8; nt++)
                    MMA(acc[mt][nt], ah[mt], (&bh[nt >> 1][(nt & 1) * 2]));
#pragma unroll
            for (int mt = 0; mt < 4; mt++)
#pragma unroll
                for (int nt = 0; nt < 8; nt++)
                    MMA(acc[mt][nt], ah[mt], (&bl[nt >> 1][(nt & 1) * 2]));
#pragma unroll
            for (int mt = 0; mt < 4; mt++)
#pragma unroll
                for (int nt = 0; nt < 8; nt++)
                    MMA(acc[mt][nt], al[mt], (&bh[nt >> 1][(nt & 1) * 2]));
        }
        if (c < NCHUNK - NSTAGE) {
            __syncwarp();
            if (lane == 0) mbar_arrive(mbE + 8*s);
            if (tid == 0) { mbar_wait(mbE + 8*s, par); ISSUE(c + NSTAGE, s); }
        }
    }

    // all warps must finish reading stage smem before we reuse it below
    __syncthreads();

    // ---------------- epilogue: column max -> exp -> smem -> coalesced stores
    const int g   = lane >> 2;
    const int tig = lane & 3;

    float cm[8][2], cs[8][2];
#pragma unroll
    for (int nt = 0; nt < 8; nt++)
#pragma unroll
        for (int e = 0; e < 2; e++) {
            float m = -INFINITY;
#pragma unroll
            for (int mt = 0; mt < 4; mt++) {
                m = fmaxf(m, acc[mt][nt][e]);
                m = fmaxf(m, acc[mt][nt][2 + e]);
            }
            cm[nt][e] = m;
        }
#pragma unroll
    for (int d = 4; d <= 16; d <<= 1)
#pragma unroll
        for (int nt = 0; nt < 8; nt++)
#pragma unroll
            for (int e = 0; e < 2; e++)
                cm[nt][e] = fmaxf(cm[nt][e], __shfl_xor_sync(0xffffffffu, cm[nt][e], d));

    // exp + partial sums, tile staged in (now safely dead) stage-0 smem.
    // smem row = 256B; byte-in-row swizzled with ((row&7)<<4).
#pragma unroll
    for (int nt = 0; nt < 8; nt++) { cs[nt][0] = 0.f; cs[nt][1] = 0.f; }
    const uint32_t gsw = (uint32_t)(g << 4);
#pragma unroll
    for (int mt = 0; mt < 4; mt++)
#pragma unroll
        for (int nt = 0; nt < 8; nt++) {
            const int r0 = wm*64 + mt*16 + g;
            const uint32_t colb = (uint32_t)(wn*128 + nt*16 + tig*4);
            const float e0 = __expf(acc[mt][nt][0] - cm[nt][0]);
            const float e1 = __expf(acc[mt][nt][1] - cm[nt][1]);
            const float e2 = __expf(acc[mt][nt][2] - cm[nt][0]);
            const float e3 = __expf(acc[mt][nt][3] - cm[nt][1]);
            cs[nt][0] += e0 + e2;
            cs[nt][1] += e1 + e3;
            const uint32_t p01 = h2_bits(__floats2half2_rn(e0, e1));
            const uint32_t p23 = h2_bits(__floats2half2_rn(e2, e3));
            const uint32_t a0 = base + (uint32_t)(r0 * 256)       + (colb ^ gsw);
            const uint32_t a1 = base + (uint32_t)((r0 + 8) * 256) + (colb ^ gsw);
            asm volatile("st.shared.b32 [%0], %1;" :: "r"(a0), "r"(p01) : "memory");
            asm volatile("st.shared.b32 [%0], %1;" :: "r"(a1), "r"(p23) : "memory");
        }
#pragma unroll
    for (int d = 4; d <= 16; d <<= 1)
#pragma unroll
        for (int nt = 0; nt < 8; nt++)
#pragma unroll
            for (int e = 0; e < 2; e++)
                cs[nt][e] += __shfl_xor_sync(0xffffffffu, cs[nt][e], d);

    if (lane < 4) {
        const int split = it*2 + wm;
#pragma unroll
        for (int nt = 0; nt < 8; nt++)
#pragma unroll
            for (int e = 0; e < 2; e++) {
                const int jg = jt*128 + wn*64 + nt*8 + lane*2 + e;
                const size_t po = ((size_t)split*BATCH + b)*HW + jg;
                g_pm[po] = cm[nt][e];
                g_ps[po] = cs[nt][e];
            }
    }

    __syncthreads();

    // coalesced fp16 tile store: each warp streams 32 rows, 2 rows per instr
    __half* eb = g_e + (size_t)b*HW*HW + (size_t)(it*128)*HW + jt*128;
    const int half16 = lane & 15;          // 16B unit within row
    const int rsub   = lane >> 4;          // 0..1
#pragma unroll
    for (int r = 0; r < 16; r++) {
        const int row = wid*32 + r*2 + rsub;
        const uint32_t sa = base + (uint32_t)(row * 256) +
                            ((uint32_t)(half16 * 16) ^ ((uint32_t)(row & 7) << 4));
        uint4 v;
        asm volatile("ld.shared.v4.b32 {%0,%1,%2,%3}, [%4];"
                     : "=r"(v.x), "=r"(v.y), "=r"(v.z), "=r"(v.w) : "r"(sa));
        *(uint4*)(eb + (size_t)row * HW + half16 * 8) = v;
    }
}

// ------------------------------------------------------------------ merge
__global__ __launch_bounds__(256) void merge_stats()
{
    const int idx = blockIdx.x * 256 + threadIdx.x;   // b*HW + j
    float m = -INFINITY;
#pragma unroll 8
    for (int s = 0; s < NSPLIT; s++)
        m = fmaxf(m, g_pm[(size_t)s * BATCH * HW + idx]);
    float sum = 0.f;
#pragma unroll 8
    for (int s = 0; s < NSPLIT; s++)
        sum += g_ps[(size_t)s * BATCH * HW + idx] *
               __expf(g_pm[(size_t)s * BATCH * HW + idx] - m);
    const float inv = 1.f / sum;
#pragma unroll 8
    for (int s = 0; s < NSPLIT; s++)
        g_sc[(size_t)s * BATCH * HW + idx] =
            __expf(g_pm[(size_t)s * BATCH * HW + idx] - m) * inv;
}

// ------------------------------------------------------------------ finalize
__global__ __launch_bounds__(256) void finalize(float* __restrict__ out)
{
    const size_t q = ((size_t)blockIdx.x * 256 + threadIdx.x) * 8;
    const int j = (int)(q & (HW - 1));
    const int i = (int)((q >> 12) & (HW - 1));
    const int b = (int)(q >> 24);

    const uint4 eraw = *(const uint4*)(g_e + q);
    const float* sc = g_sc + (size_t)(i >> 6) * BATCH * HW + (size_t)b * HW + j;
    const float4 s0 = *(const float4*)(sc);
    const float4 s1 = *(const float4*)(sc + 4);

    const float2 p0 = __half22float2(*(const __half2*)&eraw.x);
    const float2 p1 = __half22float2(*(const __half2*)&eraw.y);
    const float2 p2 = __half22float2(*(const __half2*)&eraw.z);
    const float2 p3 = __half22float2(*(const __half2*)&eraw.w);

    float4 o0, o1;
    o0.x = p0.x * s0.x;  o0.y = p0.y * s0.y;
    o0.z = p1.x * s0.z;  o0.w = p1.y * s0.w;
    o1.x = p2.x * s1.x;  o1.y = p2.y * s1.y;
    o1.z = p3.x * s1.z;  o1.w = p3.y * s1.w;

    *(float4*)(out + q)     = o0;
    *(float4*)(out + q + 4) = o1;
}

// ------------------------------------------------------------------
extern "C" void kernel_launch(void* const* d_in, const int* in_sizes, int n_in,
                              void* d_out, int out_size)
{
    const float* f1 = (const float*)d_in[0];
    const float* f2 = (const float*)d_in[1];
    float* out = (float*)d_out;

    static bool smem_set = false;
    if (!smem_set) {
        cudaFuncSetAttribute(corr_mma, cudaFuncAttributeMaxDynamicSharedMemorySize, SMEM_REQ);
        smem_set = true;
    }

    split_prep<<<2048, 256>>>(f1, f2);

    dim3 g(HW / 128, HW / 128, BATCH);           // 32 x 32 x 4
    corr_mma<<<g, 128, SMEM_REQ>>>();

    merge_stats<<<(BATCH * HW) / 256, 256>>>();

    const size_t total = (size_t)BATCH * HW * HW;
    finalize<<<(unsigned)(total / 8 / 256), 256>>>(out);
}

// round 15
// speedup vs baseline: 1.0128x; 1.0128x over previous
#include <cuda_runtime.h>
#include <cuda_bf16.h>
#include <cuda_fp16.h>
#include <math.h>
#include <stdint.h>

#define BATCH 4
#define CH    256
#define HW    4096
#define NSPLIT 64            // 32 i-tiles * 2 m-warps (split = i >> 6)
#define NCHUNK 8             // K chunks of 32 channels
#define STAGEB 32768         // A(16K: hi8|lo8) | B(16K: hi8|lo8)
#define NSTAGE 3
#define SMEM_REQ (NSTAGE*STAGEB + 1024 + 128)

// staging: per (b, cc, ib128): 16KB block = [hi 8KB | lo 8KB], rows of 64B slot-swizzled
__device__ __nv_bfloat16 g_A[BATCH*NCHUNK*HW*64];    // feat1 (i rows)
__device__ __nv_bfloat16 g_B[BATCH*NCHUNK*HW*64];    // feat2 (j rows)

__device__ __half g_e[(size_t)BATCH*HW*HW];          // exp(x - m_split), fp16
__device__ float g_pm[NSPLIT*BATCH*HW];
__device__ float g_ps[NSPLIT*BATCH*HW];
__device__ float g_sc[NSPLIT*BATCH*HW];              // exp(m_split-m)*inv

// ------------------------------------------------------------------ helpers
static __device__ __forceinline__ uint32_t smem_u32(const void* p){
    uint32_t a;
    asm("{ .reg .u64 t; cvta.to.shared.u64 t, %1; cvt.u32.u64 %0, t; }" : "=r"(a) : "l"(p));
    return a;
}
static __device__ __forceinline__ void mbar_init(uint32_t a, uint32_t c){
    asm volatile("mbarrier.init.shared.b64 [%0], %1;" :: "r"(a), "r"(c) : "memory");
}
static __device__ __forceinline__ void mbar_expect(uint32_t a, uint32_t tx){
    asm volatile("mbarrier.arrive.expect_tx.shared.b64 _, [%0], %1;" :: "r"(a), "r"(tx) : "memory");
}
static __device__ __forceinline__ void mbar_arrive(uint32_t a){
    asm volatile("mbarrier.arrive.shared.b64 _, [%0];" :: "r"(a) : "memory");
}
static __device__ __forceinline__ void mbar_wait(uint32_t a, uint32_t par){
    asm volatile("{\n\t.reg .pred P;\n\t"
                 "WL_%=:\n\t"
                 "mbarrier.try_wait.parity.acquire.cta.shared::cta.b64 P, [%0], %1, 0x989680;\n\t"
                 "@P bra WD_%=;\n\t"
                 "bra WL_%=;\n\t"
                 "WD_%=:\n\t}" :: "r"(a), "r"(par) : "memory");
}
static __device__ __forceinline__ void bulk_g2s(uint32_t dst, const void* src,
                                                uint32_t bytes, uint32_t mbar){
    asm volatile("cp.async.bulk.shared::cluster.global.mbarrier::complete_tx::bytes "
                 "[%0], [%1], %2, [%3];"
                 :: "r"(dst), "l"(src), "r"(bytes), "r"(mbar) : "memory");
}

#define LDSM4(r, addr) \
    asm volatile("ldmatrix.sync.aligned.m8n8.x4.shared.b16 {%0,%1,%2,%3}, [%4];" \
        : "=r"((r)[0]), "=r"((r)[1]), "=r"((r)[2]), "=r"((r)[3]) : "r"(addr))

#define MMA(d, a, bb) \
    asm volatile("mma.sync.aligned.m16n8k16.row.col.f32.bf16.bf16.f32 " \
        "{%0,%1,%2,%3},{%4,%5,%6,%7},{%8,%9},{%0,%1,%2,%3};" \
        : "+f"((d)[0]), "+f"((d)[1]), "+f"((d)[2]), "+f"((d)[3]) \
        : "r"((a)[0]), "r"((a)[1]), "r"((a)[2]), "r"((a)[3]), "r"((bb)[0]), "r"((bb)[1]))

// ------------------------------------------------------------------ pre-pass
__global__ __launch_bounds__(256) void split_prep(const float* __restrict__ f1,
                                                  const float* __restrict__ f2)
{
    __shared__ float s[32][129];
    const int bid = blockIdx.x;
    const int ib  = bid & 31;
    const int cc  = (bid >> 5) & 7;
    const int b   = (bid >> 8) & 3;
    const int arr = bid >> 10;
    const float* in = arr ? f2 : f1;
    __nv_bfloat16* o = arr ? g_B : g_A;
    const int t = threadIdx.x;

#pragma unroll
    for (int k = 0; k < 4; k++) {
        const int lin = k * 256 + t;
        const int c   = lin >> 5;
        const int x4  = lin & 31;
        const float4 v = *(const float4*)(in + ((size_t)(b*CH + cc*32 + c))*HW + ib*128 + x4*4);
        s[c][x4*4+0] = v.x; s[c][x4*4+1] = v.y; s[c][x4*4+2] = v.z; s[c][x4*4+3] = v.w;
    }
    __syncthreads();

    const int slot = t & 3;
    const size_t blk = (((size_t)(b*NCHUNK + cc))*32 + ib) * 16384;
#pragma unroll
    for (int rr = 0; rr < 2; rr++) {
        const int row = rr * 64 + (t >> 2);
        const uint32_t byte = (uint32_t)(row * 64) +
                              ((uint32_t)(slot << 4) ^ (uint32_t)(((row >> 1) & 3) << 4));
        uint32_t hp[4], lp[4];
#pragma unroll
        for (int u = 0; u < 4; u++) {
            const int c = slot*8 + u*2;
            const float v0 = s[c][row], v1 = s[c+1][row];
            const __nv_bfloat16 h0 = __float2bfloat16(v0);
            const __nv_bfloat16 h1 = __float2bfloat16(v1);
            const __nv_bfloat16 l0 = __float2bfloat16(v0 - __bfloat162float(h0));
            const __nv_bfloat16 l1 = __float2bfloat16(v1 - __bfloat162float(h1));
            hp[u] = ((uint32_t)__bfloat16_as_ushort(h1) << 16) | __bfloat16_as_ushort(h0);
            lp[u] = ((uint32_t)__bfloat16_as_ushort(l1) << 16) | __bfloat16_as_ushort(l0);
        }
        *(uint4*)((char*)o + blk        + byte) = make_uint4(hp[0], hp[1], hp[2], hp[3]);
        *(uint4*)((char*)o + blk + 8192 + byte) = make_uint4(lp[0], lp[1], lp[2], lp[3]);
    }
}

// ------------------------------------------------------------------ GEMM
// C[i,j] tile 128x128, 128 threads, bf16-3x, 3-stage pipeline, 2 CTAs/SM.
// Epilogue stores exp(x - m_split) as fp16 + per-column partial stats.
__global__ __launch_bounds__(128, 2) void corr_mma()
{
    extern __shared__ char dsm[];
    uint32_t base = smem_u32(dsm);
    base = (base + 1023) & ~1023u;
    const uint32_t mbF = base + NSTAGE * STAGEB;
    const uint32_t mbE = mbF + 24;

    const int tid  = threadIdx.x;
    const int lane = tid & 31;
    const int wid  = tid >> 5;
    const int wm   = wid >> 1;
    const int wn   = wid & 1;
    const int jt = blockIdx.x, it = blockIdx.y, b = blockIdx.z;

    if (tid == 0) {
#pragma unroll
        for (int s = 0; s < NSTAGE; s++) { mbar_init(mbF + 8*s, 1); mbar_init(mbE + 8*s, 4); }
        asm volatile("fence.proxy.async.shared::cta;" ::: "memory");
    }
    __syncthreads();

    #define ISSUE(c, s) do { \
        const size_t offA = (((size_t)(b*NCHUNK + (c)))*32 + it) * 16384; \
        const size_t offB = (((size_t)(b*NCHUNK + (c)))*32 + jt) * 16384; \
        mbar_expect(mbF + 8*(s), STAGEB); \
        bulk_g2s(base + (s)*STAGEB +     0, (const char*)g_A + offA, 16384, mbF + 8*(s)); \
        bulk_g2s(base + (s)*STAGEB + 16384, (const char*)g_B + offB, 16384, mbF + 8*(s)); \
    } while (0)

    if (tid == 0) { ISSUE(0,0); ISSUE(1,1); ISSUE(2,2); }

    float acc[4][8][4];
#pragma unroll
    for (int mt = 0; mt < 4; mt++)
#pragma unroll
        for (int nt = 0; nt < 8; nt++)
#pragma unroll
            for (int e = 0; e < 4; e++) acc[mt][nt][e] = 0.f;

    const int rA  = lane & 15;
    const int khA = (lane & 16) ? 16 : 0;
    const int rB  = (lane & 7) + ((lane & 16) ? 8 : 0);
    const int khB = (lane & 8)  ? 16 : 0;
    const uint32_t swA = (uint32_t)(((rA >> 1) & 3) << 4);
    const uint32_t swB = (uint32_t)(((rB >> 1) & 3) << 4);
    const uint32_t rowAoff = (uint32_t)((wm*64 + rA) * 64);
    const uint32_t rowBoff = (uint32_t)(16384 + (wn*64 + rB) * 64);

    for (int c = 0; c < NCHUNK; c++) {
        const int s = c % NSTAGE;
        const uint32_t par = (uint32_t)((c / NSTAGE) & 1);
        mbar_wait(mbF + 8*s, par);

        const uint32_t aAh = base + s*STAGEB + rowAoff;
        const uint32_t aAl = aAh + 8192;
        const uint32_t aBh = base + s*STAGEB + rowBoff;
        const uint32_t aBl = aBh + 8192;

#pragma unroll
        for (int kk = 0; kk < 2; kk++) {
            const uint32_t colA = ((uint32_t)(kk*32 + khA)) ^ swA;
            const uint32_t colB = ((uint32_t)(kk*32 + khB)) ^ swB;
            uint32_t ah[4][4], al[4][4], bh[4][4], bl[4][4];
#pragma unroll
            for (int mt = 0; mt < 4; mt++) {
                LDSM4(ah[mt], aAh + mt*1024 + colA);
                LDSM4(al[mt], aAl + mt*1024 + colA);
            }
#pragma unroll
            for (int np = 0; np < 4; np++) {
                LDSM4(bh[np], aBh + np*1024 + colB);
                LDSM4(bl[np], aBl + np*1024 + colB);
            }
#pragma unroll
            for (int mt = 0; mt < 4; mt++)
#pragma unroll
                for (int nt = 0; nt < 8; nt++)
                    MMA(acc[mt][nt], ah[mt], (&bh[nt >> 1][(nt & 1) * 2]));
#pragma unroll
            for (int mt = 0; mt < 4; mt++)
#pragma unroll
                for (int nt = 0; nt < 8; nt++)
                    MMA(acc[mt][nt], ah[mt], (&bl[nt >> 1][(nt & 1) * 2]));
#pragma unroll
            for (int mt = 0; mt < 4; mt++)
#pragma unroll
                for (int nt = 0; nt < 8; nt++)
                    MMA(acc[mt][nt], al[mt], (&bh[nt >> 1][(nt & 1) * 2]));
        }
        if (c < NCHUNK - NSTAGE) {
            __syncwarp();
            if (lane == 0) mbar_arrive(mbE + 8*s);
            if (tid == 0) { mbar_wait(mbE + 8*s, par); ISSUE(c + NSTAGE, s); }
        }
    }

    // ---------------- epilogue: column max -> exp -> fp16 store + partial sums
    const int g   = lane >> 2;
    const int tig = lane & 3;

    float cm[8][2], cs[8][2];
#pragma unroll
    for (int nt = 0; nt < 8; nt++)
#pragma unroll
        for (int e = 0; e < 2; e++) {
            float m = -INFINITY;
#pragma unroll
            for (int mt = 0; mt < 4; mt++) {
                m = fmaxf(m, acc[mt][nt][e]);
                m = fmaxf(m, acc[mt][nt][2 + e]);
            }
            cm[nt][e] = m;
        }
#pragma unroll
    for (int d = 4; d <= 16; d <<= 1)
#pragma unroll
        for (int nt = 0; nt < 8; nt++)
#pragma unroll
            for (int e = 0; e < 2; e++)
                cm[nt][e] = fmaxf(cm[nt][e], __shfl_xor_sync(0xffffffffu, cm[nt][e], d));

    __half* eb = g_e + (size_t)b*HW*HW + (size_t)(it*128)*HW + jt*128;
#pragma unroll
    for (int nt = 0; nt < 8; nt++) { cs[nt][0] = 0.f; cs[nt][1] = 0.f; }
#pragma unroll
    for (int mt = 0; mt < 4; mt++)
#pragma unroll
        for (int nt = 0; nt < 8; nt++) {
            const int r0 = wm*64 + mt*16 + g;
            const int cc = wn*64 + nt*8 + tig*2;
            const float e0 = __expf(acc[mt][nt][0] - cm[nt][0]);
            const float e1 = __expf(acc[mt][nt][1] - cm[nt][1]);
            const float e2 = __expf(acc[mt][nt][2] - cm[nt][0]);
            const float e3 = __expf(acc[mt][nt][3] - cm[nt][1]);
            cs[nt][0] += e0 + e2;
            cs[nt][1] += e1 + e3;
            *(__half2*)(eb + (size_t)r0     * HW + cc) = __floats2half2_rn(e0, e1);
            *(__half2*)(eb + (size_t)(r0+8) * HW + cc) = __floats2half2_rn(e2, e3);
        }
#pragma unroll
    for (int d = 4; d <= 16; d <<= 1)
#pragma unroll
        for (int nt = 0; nt < 8; nt++)
#pragma unroll
            for (int e = 0; e < 2; e++)
                cs[nt][e] += __shfl_xor_sync(0xffffffffu, cs[nt][e], d);

    if (lane < 4) {
        const int split = it*2 + wm;
#pragma unroll
        for (int nt = 0; nt < 8; nt++)
#pragma unroll
            for (int e = 0; e < 2; e++) {
                const int jg = jt*128 + wn*64 + nt*8 + lane*2 + e;
                const size_t po = ((size_t)split*BATCH + b)*HW + jg;
                g_pm[po] = cm[nt][e];
                g_ps[po] = cs[nt][e];
            }
    }
}

// ------------------------------------------------------------------ merge
// global max + sum per column, then per-split scale sc = exp(pm-m)/sum
__global__ __launch_bounds__(256) void merge_stats()
{
    const int idx = blockIdx.x * 256 + threadIdx.x;   // b*HW + j
    float pm[NSPLIT];
    float m = -INFINITY;
#pragma unroll 8
    for (int s = 0; s < NSPLIT; s++) {
        pm[s] = __ldcs(&g_pm[(size_t)s * BATCH * HW + idx]);
        m = fmaxf(m, pm[s]);
    }
    float sum = 0.f;
#pragma unroll 8
    for (int s = 0; s < NSPLIT; s++)
        sum += __ldcs(&g_ps[(size_t)s * BATCH * HW + idx]) * __expf(pm[s] - m);
    const float inv = 1.f / sum;
#pragma unroll 8
    for (int s = 0; s < NSPLIT; s++)
        g_sc[(size_t)s * BATCH * HW + idx] = __expf(pm[s] - m) * inv;
}

// ------------------------------------------------------------------ finalize
// out[b,i,j] = (float)g_e[b,i,j] * g_sc[i>>6][b][j]; streaming hints
__global__ __launch_bounds__(256) void finalize(float* __restrict__ out)
{
    const size_t q = ((size_t)blockIdx.x * 256 + threadIdx.x) * 8;
    const int j = (int)(q & (HW - 1));
    const int i = (int)((q >> 12) & (HW - 1));
    const int b = (int)(q >> 24);

    const uint4 eraw = __ldcs((const uint4*)(g_e + q));     // evict-first read
    const float* sc = g_sc + (size_t)(i >> 6) * BATCH * HW + (size_t)b * HW + j;
    const float4 s0 = *(const float4*)(sc);
    const float4 s1 = *(const float4*)(sc + 4);

    const float2 p0 = __half22float2(*(const __half2*)&eraw.x);
    const float2 p1 = __half22float2(*(const __half2*)&eraw.y);
    const float2 p2 = __half22float2(*(const __half2*)&eraw.z);
    const float2 p3 = __half22float2(*(const __half2*)&eraw.w);

    float4 o0, o1;
    o0.x = p0.x * s0.x;  o0.y = p0.y * s0.y;
    o0.z = p1.x * s0.z;  o0.w = p1.y * s0.w;
    o1.x = p2.x * s1.x;  o1.y = p2.y * s1.y;
    o1.z = p3.x * s1.z;  o1.w = p3.y * s1.w;

    __stcs((float4*)(out + q),     o0);                     // evict-first write
    __stcs((float4*)(out + q + 4), o1);
}

// ------------------------------------------------------------------
extern "C" void kernel_launch(void* const* d_in, const int* in_sizes, int n_in,
                              void* d_out, int out_size)
{
    const float* f1 = (const float*)d_in[0];
    const float* f2 = (const float*)d_in[1];
    float* out = (float*)d_out;

    static bool smem_set = false;
    if (!smem_set) {
        cudaFuncSetAttribute(corr_mma, cudaFuncAttributeMaxDynamicSharedMemorySize, SMEM_REQ);
        smem_set = true;
    }

    split_prep<<<2048, 256>>>(f1, f2);

    dim3 g(HW / 128, HW / 128, BATCH);           // 32 x 32 x 4
    corr_mma<<<g, 128, SMEM_REQ>>>();

    merge_stats<<<(BATCH * HW) / 256, 256>>>();

    const size_t total = (size_t)BATCH * HW * HW;
    finalize<<<(unsigned)(total / 8 / 256), 256>>>(out);
}

// round 16
// speedup vs baseline: 1.0204x; 1.0074x over previous
#include <cuda_runtime.h>
#include <cuda_bf16.h>
#include <cuda_fp16.h>
#include <math.h>
#include <stdint.h>

#define BATCH 4
#define CH    256
#define HW    4096
#define NSPLIT 64            // 32 i-tiles * 2 m-warps (split = i >> 6)
#define NCHUNK 8             // K chunks of 32 channels
#define STAGEB 32768         // A(16K: hi8|lo8) | B(16K: hi8|lo8)
#define NSTAGE 3
#define SMEM_REQ (NSTAGE*STAGEB + 1024 + 128)

// staging: per (b, cc, ib128): 16KB block = [hi 8KB | lo 8KB], rows of 64B slot-swizzled
__device__ __nv_bfloat16 g_A[BATCH*NCHUNK*HW*64];    // feat1 (i rows)
__device__ __nv_bfloat16 g_B[BATCH*NCHUNK*HW*64];    // feat2 (j rows)

__device__ __half g_e[(size_t)BATCH*HW*HW];          // exp(x - m_split), fp16
__device__ float g_pm[NSPLIT*BATCH*HW];
__device__ float g_ps[NSPLIT*BATCH*HW];
__device__ float g_sc[NSPLIT*BATCH*HW];              // exp(m_split-m)*inv

// ------------------------------------------------------------------ helpers
static __device__ __forceinline__ uint32_t smem_u32(const void* p){
    uint32_t a;
    asm("{ .reg .u64 t; cvta.to.shared.u64 t, %1; cvt.u32.u64 %0, t; }" : "=r"(a) : "l"(p));
    return a;
}
static __device__ __forceinline__ void mbar_init(uint32_t a, uint32_t c){
    asm volatile("mbarrier.init.shared.b64 [%0], %1;" :: "r"(a), "r"(c) : "memory");
}
static __device__ __forceinline__ void mbar_expect(uint32_t a, uint32_t tx){
    asm volatile("mbarrier.arrive.expect_tx.shared.b64 _, [%0], %1;" :: "r"(a), "r"(tx) : "memory");
}
static __device__ __forceinline__ void mbar_arrive(uint32_t a){
    asm volatile("mbarrier.arrive.shared.b64 _, [%0];" :: "r"(a) : "memory");
}
static __device__ __forceinline__ void mbar_wait(uint32_t a, uint32_t par){
    asm volatile("{\n\t.reg .pred P;\n\t"
                 "WL_%=:\n\t"
                 "mbarrier.try_wait.parity.acquire.cta.shared::cta.b64 P, [%0], %1, 0x989680;\n\t"
                 "@P bra WD_%=;\n\t"
                 "bra WL_%=;\n\t"
                 "WD_%=:\n\t}" :: "r"(a), "r"(par) : "memory");
}
static __device__ __forceinline__ void bulk_g2s(uint32_t dst, const void* src,
                                                uint32_t bytes, uint32_t mbar){
    asm volatile("cp.async.bulk.shared::cluster.global.mbarrier::complete_tx::bytes "
                 "[%0], [%1], %2, [%3];"
                 :: "r"(dst), "l"(src), "r"(bytes), "r"(mbar) : "memory");
}

#define LDSM4(r, addr) \
    asm volatile("ldmatrix.sync.aligned.m8n8.x4.shared.b16 {%0,%1,%2,%3}, [%4];" \
        : "=r"((r)[0]), "=r"((r)[1]), "=r"((r)[2]), "=r"((r)[3]) : "r"(addr))

#define MMA(d, a, bb) \
    asm volatile("mma.sync.aligned.m16n8k16.row.col.f32.bf16.bf16.f32 " \
        "{%0,%1,%2,%3},{%4,%5,%6,%7},{%8,%9},{%0,%1,%2,%3};" \
        : "+f"((d)[0]), "+f"((d)[1]), "+f"((d)[2]), "+f"((d)[3]) \
        : "r"((a)[0]), "r"((a)[1]), "r"((a)[2]), "r"((a)[3]), "r"((bb)[0]), "r"((bb)[1]))

// ------------------------------------------------------------------ pre-pass
__global__ __launch_bounds__(256) void split_prep(const float* __restrict__ f1,
                                                  const float* __restrict__ f2)
{
    __shared__ float s[32][129];
    const int bid = blockIdx.x;
    const int ib  = bid & 31;
    const int cc  = (bid >> 5) & 7;
    const int b   = (bid >> 8) & 3;
    const int arr = bid >> 10;
    const float* in = arr ? f2 : f1;
    __nv_bfloat16* o = arr ? g_B : g_A;
    const int t = threadIdx.x;

#pragma unroll
    for (int k = 0; k < 4; k++) {
        const int lin = k * 256 + t;
        const int c   = lin >> 5;
        const int x4  = lin & 31;
        const float4 v = *(const float4*)(in + ((size_t)(b*CH + cc*32 + c))*HW + ib*128 + x4*4);
        s[c][x4*4+0] = v.x; s[c][x4*4+1] = v.y; s[c][x4*4+2] = v.z; s[c][x4*4+3] = v.w;
    }
    __syncthreads();

    const int slot = t & 3;
    const size_t blk = (((size_t)(b*NCHUNK + cc))*32 + ib) * 16384;
#pragma unroll
    for (int rr = 0; rr < 2; rr++) {
        const int row = rr * 64 + (t >> 2);
        const uint32_t byte = (uint32_t)(row * 64) +
                              ((uint32_t)(slot << 4) ^ (uint32_t)(((row >> 1) & 3) << 4));
        uint32_t hp[4], lp[4];
#pragma unroll
        for (int u = 0; u < 4; u++) {
            const int c = slot*8 + u*2;
            const float v0 = s[c][row], v1 = s[c+1][row];
            const __nv_bfloat16 h0 = __float2bfloat16(v0);
            const __nv_bfloat16 h1 = __float2bfloat16(v1);
            const __nv_bfloat16 l0 = __float2bfloat16(v0 - __bfloat162float(h0));
            const __nv_bfloat16 l1 = __float2bfloat16(v1 - __bfloat162float(h1));
            hp[u] = ((uint32_t)__bfloat16_as_ushort(h1) << 16) | __bfloat16_as_ushort(h0);
            lp[u] = ((uint32_t)__bfloat16_as_ushort(l1) << 16) | __bfloat16_as_ushort(l0);
        }
        *(uint4*)((char*)o + blk        + byte) = make_uint4(hp[0], hp[1], hp[2], hp[3]);
        *(uint4*)((char*)o + blk + 8192 + byte) = make_uint4(lp[0], lp[1], lp[2], lp[3]);
    }
}

// ------------------------------------------------------------------ GEMM
// C[i,j] tile 128x128, 128 threads, bf16-3x, 3-stage pipeline, 2 CTAs/SM.
// PDL: prologue runs during split_prep's tail; sync before first TMA.
__global__ __launch_bounds__(128, 2) void corr_mma()
{
    extern __shared__ char dsm[];
    uint32_t base = smem_u32(dsm);
    base = (base + 1023) & ~1023u;
    const uint32_t mbF = base + NSTAGE * STAGEB;
    const uint32_t mbE = mbF + 24;

    const int tid  = threadIdx.x;
    const int lane = tid & 31;
    const int wid  = tid >> 5;
    const int wm   = wid >> 1;
    const int wn   = wid & 1;
    const int jt = blockIdx.x, it = blockIdx.y, b = blockIdx.z;

    if (tid == 0) {
#pragma unroll
        for (int s = 0; s < NSTAGE; s++) { mbar_init(mbF + 8*s, 1); mbar_init(mbE + 8*s, 4); }
        asm volatile("fence.proxy.async.shared::cta;" ::: "memory");
    }
    __syncthreads();

    // wait for split_prep's writes before TMA reads g_A/g_B
    cudaGridDependencySynchronize();

    #define ISSUE(c, s) do { \
        const size_t offA = (((size_t)(b*NCHUNK + (c)))*32 + it) * 16384; \
        const size_t offB = (((size_t)(b*NCHUNK + (c)))*32 + jt) * 16384; \
        mbar_expect(mbF + 8*(s), STAGEB); \
        bulk_g2s(base + (s)*STAGEB +     0, (const char*)g_A + offA, 16384, mbF + 8*(s)); \
        bulk_g2s(base + (s)*STAGEB + 16384, (const char*)g_B + offB, 16384, mbF + 8*(s)); \
    } while (0)

    if (tid == 0) { ISSUE(0,0); ISSUE(1,1); ISSUE(2,2); }

    float acc[4][8][4];
#pragma unroll
    for (int mt = 0; mt < 4; mt++)
#pragma unroll
        for (int nt = 0; nt < 8; nt++)
#pragma unroll
            for (int e = 0; e < 4; e++) acc[mt][nt][e] = 0.f;

    const int rA  = lane & 15;
    const int khA = (lane & 16) ? 16 : 0;
    const int rB  = (lane & 7) + ((lane & 16) ? 8 : 0);
    const int khB = (lane & 8)  ? 16 : 0;
    const uint32_t swA = (uint32_t)(((rA >> 1) & 3) << 4);
    const uint32_t swB = (uint32_t)(((rB >> 1) & 3) << 4);
    const uint32_t rowAoff = (uint32_t)((wm*64 + rA) * 64);
    const uint32_t rowBoff = (uint32_t)(16384 + (wn*64 + rB) * 64);

    for (int c = 0; c < NCHUNK; c++) {
        const int s = c % NSTAGE;
        const uint32_t par = (uint32_t)((c / NSTAGE) & 1);
        mbar_wait(mbF + 8*s, par);

        const uint32_t aAh = base + s*STAGEB + rowAoff;
        const uint32_t aAl = aAh + 8192;
        const uint32_t aBh = base + s*STAGEB + rowBoff;
        const uint32_t aBl = aBh + 8192;

#pragma unroll
        for (int kk = 0; kk < 2; kk++) {
            const uint32_t colA = ((uint32_t)(kk*32 + khA)) ^ swA;
            const uint32_t colB = ((uint32_t)(kk*32 + khB)) ^ swB;
            uint32_t ah[4][4], al[4][4], bh[4][4], bl[4][4];
#pragma unroll
            for (int mt = 0; mt < 4; mt++) {
                LDSM4(ah[mt], aAh + mt*1024 + colA);
                LDSM4(al[mt], aAl + mt*1024 + colA);
            }
#pragma unroll
            for (int np = 0; np < 4; np++) {
                LDSM4(bh[np], aBh + np*1024 + colB);
                LDSM4(bl[np], aBl + np*1024 + colB);
            }
#pragma unroll
            for (int mt = 0; mt < 4; mt++)
#pragma unroll
                for (int nt = 0; nt < 8; nt++)
                    MMA(acc[mt][nt], ah[mt], (&bh[nt >> 1][(nt & 1) * 2]));
#pragma unroll
            for (int mt = 0; mt < 4; mt++)
#pragma unroll
                for (int nt = 0; nt < 8; nt++)
                    MMA(acc[mt][nt], ah[mt], (&bl[nt >> 1][(nt & 1) * 2]));
#pragma unroll
            for (int mt = 0; mt < 4; mt++)
#pragma unroll
                for (int nt = 0; nt < 8; nt++)
                    MMA(acc[mt][nt], al[mt], (&bh[nt >> 1][(nt & 1) * 2]));
        }
        if (c < NCHUNK - NSTAGE) {
            __syncwarp();
            if (lane == 0) mbar_arrive(mbE + 8*s);
            if (tid == 0) { mbar_wait(mbE + 8*s, par); ISSUE(c + NSTAGE, s); }
        }
    }

    // ---------------- epilogue: column max -> exp -> fp16 store + partial sums
    const int g   = lane >> 2;
    const int tig = lane & 3;

    float cm[8][2], cs[8][2];
#pragma unroll
    for (int nt = 0; nt < 8; nt++)
#pragma unroll
        for (int e = 0; e < 2; e++) {
            float m = -INFINITY;
#pragma unroll
            for (int mt = 0; mt < 4; mt++) {
                m = fmaxf(m, acc[mt][nt][e]);
                m = fmaxf(m, acc[mt][nt][2 + e]);
            }
            cm[nt][e] = m;
        }
#pragma unroll
    for (int d = 4; d <= 16; d <<= 1)
#pragma unroll
        for (int nt = 0; nt < 8; nt++)
#pragma unroll
            for (int e = 0; e < 2; e++)
                cm[nt][e] = fmaxf(cm[nt][e], __shfl_xor_sync(0xffffffffu, cm[nt][e], d));

    __half* eb = g_e + (size_t)b*HW*HW + (size_t)(it*128)*HW + jt*128;
#pragma unroll
    for (int nt = 0; nt < 8; nt++) { cs[nt][0] = 0.f; cs[nt][1] = 0.f; }
#pragma unroll
    for (int mt = 0; mt < 4; mt++)
#pragma unroll
        for (int nt = 0; nt < 8; nt++) {
            const int r0 = wm*64 + mt*16 + g;
            const int cc = wn*64 + nt*8 + tig*2;
            const float e0 = __expf(acc[mt][nt][0] - cm[nt][0]);
            const float e1 = __expf(acc[mt][nt][1] - cm[nt][1]);
            const float e2 = __expf(acc[mt][nt][2] - cm[nt][0]);
            const float e3 = __expf(acc[mt][nt][3] - cm[nt][1]);
            cs[nt][0] += e0 + e2;
            cs[nt][1] += e1 + e3;
            *(__half2*)(eb + (size_t)r0     * HW + cc) = __floats2half2_rn(e0, e1);
            *(__half2*)(eb + (size_t)(r0+8) * HW + cc) = __floats2half2_rn(e2, e3);
        }
#pragma unroll
    for (int d = 4; d <= 16; d <<= 1)
#pragma unroll
        for (int nt = 0; nt < 8; nt++)
#pragma unroll
            for (int e = 0; e < 2; e++)
                cs[nt][e] += __shfl_xor_sync(0xffffffffu, cs[nt][e], d);

    if (lane < 4) {
        const int split = it*2 + wm;
#pragma unroll
        for (int nt = 0; nt < 8; nt++)
#pragma unroll
            for (int e = 0; e < 2; e++) {
                const int jg = jt*128 + wn*64 + nt*8 + lane*2 + e;
                const size_t po = ((size_t)split*BATCH + b)*HW + jg;
                g_pm[po] = cm[nt][e];
                g_ps[po] = cs[nt][e];
            }
    }
}

// ------------------------------------------------------------------ merge
__global__ __launch_bounds__(256) void merge_stats()
{
    cudaGridDependencySynchronize();     // wait for all GEMM partials
    const int idx = blockIdx.x * 256 + threadIdx.x;   // b*HW + j
    float m = -INFINITY;
#pragma unroll 8
    for (int s = 0; s < NSPLIT; s++)
        m = fmaxf(m, g_pm[(size_t)s * BATCH * HW + idx]);
    float sum = 0.f;
#pragma unroll 8
    for (int s = 0; s < NSPLIT; s++)
        sum += g_ps[(size_t)s * BATCH * HW + idx] *
               __expf(g_pm[(size_t)s * BATCH * HW + idx] - m);
    const float inv = 1.f / sum;
#pragma unroll 8
    for (int s = 0; s < NSPLIT; s++)
        g_sc[(size_t)s * BATCH * HW + idx] =
            __expf(g_pm[(size_t)s * BATCH * HW + idx] - m) * inv;
}

// ------------------------------------------------------------------ finalize
__global__ __launch_bounds__(256) void finalize(float* __restrict__ out)
{
    cudaGridDependencySynchronize();     // wait for merge's g_sc
    const size_t q = ((size_t)blockIdx.x * 256 + threadIdx.x) * 8;
    const int j = (int)(q & (HW - 1));
    const int i = (int)((q >> 12) & (HW - 1));
    const int b = (int)(q >> 24);

    const uint4 eraw = *(const uint4*)(g_e + q);
    const float* sc = g_sc + (size_t)(i >> 6) * BATCH * HW + (size_t)b * HW + j;
    const float4 s0 = *(const float4*)(sc);
    const float4 s1 = *(const float4*)(sc + 4);

    const float2 p0 = __half22float2(*(const __half2*)&eraw.x);
    const float2 p1 = __half22float2(*(const __half2*)&eraw.y);
    const float2 p2 = __half22float2(*(const __half2*)&eraw.z);
    const float2 p3 = __half22float2(*(const __half2*)&eraw.w);

    float4 o0, o1;
    o0.x = p0.x * s0.x;  o0.y = p0.y * s0.y;
    o0.z = p1.x * s0.z;  o0.w = p1.y * s0.w;
    o1.x = p2.x * s1.x;  o1.y = p2.y * s1.y;
    o1.z = p3.x * s1.z;  o1.w = p3.y * s1.w;

    *(float4*)(out + q)     = o0;
    *(float4*)(out + q + 4) = o1;
}

// ------------------------------------------------------------------
extern "C" void kernel_launch(void* const* d_in, const int* in_sizes, int n_in,
                              void* d_out, int out_size)
{
    const float* f1 = (const float*)d_in[0];
    const float* f2 = (const float*)d_in[1];
    float* out = (float*)d_out;

    static bool smem_set = false;
    if (!smem_set) {
        cudaFuncSetAttribute(corr_mma, cudaFuncAttributeMaxDynamicSharedMemorySize, SMEM_REQ);
        smem_set = true;
    }

    split_prep<<<2048, 256>>>(f1, f2);

    cudaLaunchAttribute pdl;
    pdl.id = cudaLaunchAttributeProgrammaticStreamSerialization;
    pdl.val.programmaticStreamSerializationAllowed = 1;

    {   // GEMM with PDL (prologue overlaps prep tail)
        cudaLaunchConfig_t cfg = {};
        cfg.gridDim = dim3(HW / 128, HW / 128, BATCH);   // 32 x 32 x 4
        cfg.blockDim = dim3(128, 1, 1);
        cfg.dynamicSmemBytes = SMEM_REQ;
        cfg.attrs = &pdl;
        cfg.numAttrs = 1;
        cudaLaunchKernelEx(&cfg, corr_mma);
    }
    {   // merge with PDL (launch overlaps GEMM tail)
        cudaLaunchConfig_t cfg = {};
        cfg.gridDim = dim3((BATCH * HW) / 256, 1, 1);
        cfg.blockDim = dim3(256, 1, 1);
        cfg.attrs = &pdl;
        cfg.numAttrs = 1;
        cudaLaunchKernelEx(&cfg, merge_stats);
    }
    {   // finalize with PDL (launch overlaps merge)
        const size_t total = (size_t)BATCH * HW * HW;
        cudaLaunchConfig_t cfg = {};
        cfg.gridDim = dim3((unsigned)(total / 8 / 256), 1, 1);
        cfg.blockDim = dim3(256, 1, 1);
        cfg.attrs = &pdl;
        cfg.numAttrs = 1;
        cudaLaunchKernelEx(&cfg, finalize, out);
    }
}

// round 17
// speedup vs baseline: 1.0302x; 1.0096x over previous
#include <cuda_runtime.h>
#include <cuda_bf16.h>
#include <cuda_fp16.h>
#include <math.h>
#include <stdint.h>

#define BATCH 4
#define CH    256
#define HW    4096
#define NSPLIT 64            // 32 i-tiles * 2 m-warps (split = i >> 6)
#define NCHUNK 8             // K chunks of 32 channels
#define STAGEB 32768         // A(16K: hi8|lo8) | B(16K: hi8|lo8)
#define NSTAGE 3
#define SMEM_REQ (NSTAGE*STAGEB + 1024 + 128)

// staging: per (b, cc, ib128): 16KB block = [hi 8KB | lo 8KB], rows of 64B slot-swizzled
__device__ __nv_bfloat16 g_A[BATCH*NCHUNK*HW*64];    // feat1 (i rows)
__device__ __nv_bfloat16 g_B[BATCH*NCHUNK*HW*64];    // feat2 (j rows)

__device__ __half g_e[(size_t)BATCH*HW*HW];          // exp(x - m_split), fp16
__device__ float g_pm[NSPLIT*BATCH*HW];
__device__ float g_ps[NSPLIT*BATCH*HW];
__device__ float g_sc[NSPLIT*BATCH*HW];              // exp(m_split-m)*inv

// ------------------------------------------------------------------ helpers
static __device__ __forceinline__ uint32_t smem_u32(const void* p){
    uint32_t a;
    asm("{ .reg .u64 t; cvta.to.shared.u64 t, %1; cvt.u32.u64 %0, t; }" : "=r"(a) : "l"(p));
    return a;
}
static __device__ __forceinline__ void mbar_init(uint32_t a, uint32_t c){
    asm volatile("mbarrier.init.shared.b64 [%0], %1;" :: "r"(a), "r"(c) : "memory");
}
static __device__ __forceinline__ void mbar_expect(uint32_t a, uint32_t tx){
    asm volatile("mbarrier.arrive.expect_tx.shared.b64 _, [%0], %1;" :: "r"(a), "r"(tx) : "memory");
}
static __device__ __forceinline__ void mbar_arrive(uint32_t a){
    asm volatile("mbarrier.arrive.shared.b64 _, [%0];" :: "r"(a) : "memory");
}
static __device__ __forceinline__ void mbar_wait(uint32_t a, uint32_t par){
    asm volatile("{\n\t.reg .pred P;\n\t"
                 "WL_%=:\n\t"
                 "mbarrier.try_wait.parity.acquire.cta.shared::cta.b64 P, [%0], %1, 0x989680;\n\t"
                 "@P bra WD_%=;\n\t"
                 "bra WL_%=;\n\t"
                 "WD_%=:\n\t}" :: "r"(a), "r"(par) : "memory");
}
static __device__ __forceinline__ void bulk_g2s(uint32_t dst, const void* src,
                                                uint32_t bytes, uint32_t mbar){
    asm volatile("cp.async.bulk.shared::cluster.global.mbarrier::complete_tx::bytes "
                 "[%0], [%1], %2, [%3];"
                 :: "r"(dst), "l"(src), "r"(bytes), "r"(mbar) : "memory");
}

#define LDSM4(r, addr) \
    asm volatile("ldmatrix.sync.aligned.m8n8.x4.shared.b16 {%0,%1,%2,%3}, [%4];" \
        : "=r"((r)[0]), "=r"((r)[1]), "=r"((r)[2]), "=r"((r)[3]) : "r"(addr))

#define MMA(d, a, bb) \
    asm volatile("mma.sync.aligned.m16n8k16.row.col.f32.bf16.bf16.f32 " \
        "{%0,%1,%2,%3},{%4,%5,%6,%7},{%8,%9},{%0,%1,%2,%3};" \
        : "+f"((d)[0]), "+f"((d)[1]), "+f"((d)[2]), "+f"((d)[3]) \
        : "r"((a)[0]), "r"((a)[1]), "r"((a)[2]), "r"((a)[3]), "r"((bb)[0]), "r"((bb)[1]))

// ------------------------------------------------------------------ pre-pass
__global__ __launch_bounds__(256) void split_prep(const float* __restrict__ f1,
                                                  const float* __restrict__ f2)
{
    __shared__ float s[32][129];
    const int bid = blockIdx.x;
    const int ib  = bid & 31;
    const int cc  = (bid >> 5) & 7;
    const int b   = (bid >> 8) & 3;
    const int arr = bid >> 10;
    const float* in = arr ? f2 : f1;
    __nv_bfloat16* o = arr ? g_B : g_A;
    const int t = threadIdx.x;

#pragma unroll
    for (int k = 0; k < 4; k++) {
        const int lin = k * 256 + t;
        const int c   = lin >> 5;
        const int x4  = lin & 31;
        const float4 v = *(const float4*)(in + ((size_t)(b*CH + cc*32 + c))*HW + ib*128 + x4*4);
        s[c][x4*4+0] = v.x; s[c][x4*4+1] = v.y; s[c][x4*4+2] = v.z; s[c][x4*4+3] = v.w;
    }
    __syncthreads();

    const int slot = t & 3;
    const size_t blk = (((size_t)(b*NCHUNK + cc))*32 + ib) * 16384;
#pragma unroll
    for (int rr = 0; rr < 2; rr++) {
        const int row = rr * 64 + (t >> 2);
        const uint32_t byte = (uint32_t)(row * 64) +
                              ((uint32_t)(slot << 4) ^ (uint32_t)(((row >> 1) & 3) << 4));
        uint32_t hp[4], lp[4];
#pragma unroll
        for (int u = 0; u < 4; u++) {
            const int c = slot*8 + u*2;
            const float v0 = s[c][row], v1 = s[c+1][row];
            const __nv_bfloat16 h0 = __float2bfloat16(v0);
            const __nv_bfloat16 h1 = __float2bfloat16(v1);
            const __nv_bfloat16 l0 = __float2bfloat16(v0 - __bfloat162float(h0));
            const __nv_bfloat16 l1 = __float2bfloat16(v1 - __bfloat162float(h1));
            hp[u] = ((uint32_t)__bfloat16_as_ushort(h1) << 16) | __bfloat16_as_ushort(h0);
            lp[u] = ((uint32_t)__bfloat16_as_ushort(l1) << 16) | __bfloat16_as_ushort(l0);
        }
        *(uint4*)((char*)o + blk        + byte) = make_uint4(hp[0], hp[1], hp[2], hp[3]);
        *(uint4*)((char*)o + blk + 8192 + byte) = make_uint4(lp[0], lp[1], lp[2], lp[3]);
    }
}

// ------------------------------------------------------------------ GEMM
// C[i,j] tile 128x128, 128 threads, bf16-3x, 3-stage pipeline, 2 CTAs/SM.
// Early empty-arrive: stage released right after its last LDSM, before the
// final MMA burst, so the TMA refill overlaps the MMA issue.
__global__ __launch_bounds__(128, 2) void corr_mma()
{
    extern __shared__ char dsm[];
    uint32_t base = smem_u32(dsm);
    base = (base + 1023) & ~1023u;
    const uint32_t mbF = base + NSTAGE * STAGEB;
    const uint32_t mbE = mbF + 24;

    const int tid  = threadIdx.x;
    const int lane = tid & 31;
    const int wid  = tid >> 5;
    const int wm   = wid >> 1;
    const int wn   = wid & 1;
    const int jt = blockIdx.x, it = blockIdx.y, b = blockIdx.z;

    if (tid == 0) {
#pragma unroll
        for (int s = 0; s < NSTAGE; s++) { mbar_init(mbF + 8*s, 1); mbar_init(mbE + 8*s, 4); }
        asm volatile("fence.proxy.async.shared::cta;" ::: "memory");
    }
    __syncthreads();

    // wait for split_prep's writes before TMA reads g_A/g_B
    cudaGridDependencySynchronize();

    #define ISSUE(c, s) do { \
        const size_t offA = (((size_t)(b*NCHUNK + (c)))*32 + it) * 16384; \
        const size_t offB = (((size_t)(b*NCHUNK + (c)))*32 + jt) * 16384; \
        mbar_expect(mbF + 8*(s), STAGEB); \
        bulk_g2s(base + (s)*STAGEB +     0, (const char*)g_A + offA, 16384, mbF + 8*(s)); \
        bulk_g2s(base + (s)*STAGEB + 16384, (const char*)g_B + offB, 16384, mbF + 8*(s)); \
    } while (0)

    if (tid == 0) { ISSUE(0,0); ISSUE(1,1); ISSUE(2,2); }

    float acc[4][8][4];
#pragma unroll
    for (int mt = 0; mt < 4; mt++)
#pragma unroll
        for (int nt = 0; nt < 8; nt++)
#pragma unroll
            for (int e = 0; e < 4; e++) acc[mt][nt][e] = 0.f;

    const int rA  = lane & 15;
    const int khA = (lane & 16) ? 16 : 0;
    const int rB  = (lane & 7) + ((lane & 16) ? 8 : 0);
    const int khB = (lane & 8)  ? 16 : 0;
    const uint32_t swA = (uint32_t)(((rA >> 1) & 3) << 4);
    const uint32_t swB = (uint32_t)(((rB >> 1) & 3) << 4);
    const uint32_t rowAoff = (uint32_t)((wm*64 + rA) * 64);
    const uint32_t rowBoff = (uint32_t)(16384 + (wn*64 + rB) * 64);

    for (int c = 0; c < NCHUNK; c++) {
        const int s = c % NSTAGE;
        const uint32_t par = (uint32_t)((c / NSTAGE) & 1);
        const bool refill = (c < NCHUNK - NSTAGE);
        mbar_wait(mbF + 8*s, par);

        const uint32_t aAh = base + s*STAGEB + rowAoff;
        const uint32_t aAl = aAh + 8192;
        const uint32_t aBh = base + s*STAGEB + rowBoff;
        const uint32_t aBl = aBh + 8192;

#pragma unroll
        for (int kk = 0; kk < 2; kk++) {
            const uint32_t colA = ((uint32_t)(kk*32 + khA)) ^ swA;
            const uint32_t colB = ((uint32_t)(kk*32 + khB)) ^ swB;
            uint32_t ah[4][4], al[4][4], bh[4][4], bl[4][4];
#pragma unroll
            for (int mt = 0; mt < 4; mt++) {
                LDSM4(ah[mt], aAh + mt*1024 + colA);
                LDSM4(al[mt], aAl + mt*1024 + colA);
            }
#pragma unroll
            for (int np = 0; np < 4; np++) {
                LDSM4(bh[np], aBh + np*1024 + colB);
                LDSM4(bl[np], aBl + np*1024 + colB);
            }
            // stage-s smem fully consumed after the kk=1 LDSMs -> release early
            if (kk == 1 && refill) {
                __syncwarp();
                if (lane == 0) mbar_arrive(mbE + 8*s);
            }
#pragma unroll
            for (int mt = 0; mt < 4; mt++)
#pragma unroll
                for (int nt = 0; nt < 8; nt++)
                    MMA(acc[mt][nt], ah[mt], (&bh[nt >> 1][(nt & 1) * 2]));
#pragma unroll
            for (int mt = 0; mt < 4; mt++)
#pragma unroll
                for (int nt = 0; nt < 8; nt++)
                    MMA(acc[mt][nt], ah[mt], (&bl[nt >> 1][(nt & 1) * 2]));
#pragma unroll
            for (int mt = 0; mt < 4; mt++)
#pragma unroll
                for (int nt = 0; nt < 8; nt++)
                    MMA(acc[mt][nt], al[mt], (&bh[nt >> 1][(nt & 1) * 2]));
        }
        if (refill && tid == 0) {
            mbar_wait(mbE + 8*s, par);
            ISSUE(c + NSTAGE, s);
        }
    }

    // ---------------- epilogue: column max -> exp -> fp16 store + partial sums
    const int g   = lane >> 2;
    const int tig = lane & 3;

    float cm[8][2], cs[8][2];
#pragma unroll
    for (int nt = 0; nt < 8; nt++)
#pragma unroll
        for (int e = 0; e < 2; e++) {
            float m = -INFINITY;
#pragma unroll
            for (int mt = 0; mt < 4; mt++) {
                m = fmaxf(m, acc[mt][nt][e]);
                m = fmaxf(m, acc[mt][nt][2 + e]);
            }
            cm[nt][e] = m;
        }
#pragma unroll
    for (int d = 4; d <= 16; d <<= 1)
#pragma unroll
        for (int nt = 0; nt < 8; nt++)
#pragma unroll
            for (int e = 0; e < 2; e++)
                cm[nt][e] = fmaxf(cm[nt][e], __shfl_xor_sync(0xffffffffu, cm[nt][e], d));

    __half* eb = g_e + (size_t)b*HW*HW + (size_t)(it*128)*HW + jt*128;
#pragma unroll
    for (int nt = 0; nt < 8; nt++) { cs[nt][0] = 0.f; cs[nt][1] = 0.f; }
#pragma unroll
    for (int mt = 0; mt < 4; mt++)
#pragma unroll
        for (int nt = 0; nt < 8; nt++) {
            const int r0 = wm*64 + mt*16 + g;
            const int cc = wn*64 + nt*8 + tig*2;
            const float e0 = __expf(acc[mt][nt][0] - cm[nt][0]);
            const float e1 = __expf(acc[mt][nt][1] - cm[nt][1]);
            const float e2 = __expf(acc[mt][nt][2] - cm[nt][0]);
            const float e3 = __expf(acc[mt][nt][3] - cm[nt][1]);
            cs[nt][0] += e0 + e2;
            cs[nt][1] += e1 + e3;
            *(__half2*)(eb + (size_t)r0     * HW + cc) = __floats2half2_rn(e0, e1);
            *(__half2*)(eb + (size_t)(r0+8) * HW + cc) = __floats2half2_rn(e2, e3);
        }
#pragma unroll
    for (int d = 4; d <= 16; d <<= 1)
#pragma unroll
        for (int nt = 0; nt < 8; nt++)
#pragma unroll
            for (int e = 0; e < 2; e++)
                cs[nt][e] += __shfl_xor_sync(0xffffffffu, cs[nt][e], d);

    if (lane < 4) {
        const int split = it*2 + wm;
#pragma unroll
        for (int nt = 0; nt < 8; nt++)
#pragma unroll
            for (int e = 0; e < 2; e++) {
                const int jg = jt*128 + wn*64 + nt*8 + lane*2 + e;
                const size_t po = ((size_t)split*BATCH + b)*HW + jg;
                g_pm[po] = cm[nt][e];
                g_ps[po] = cs[nt][e];
            }
    }
}

// ------------------------------------------------------------------ merge
__global__ __launch_bounds__(256) void merge_stats()
{
    cudaGridDependencySynchronize();     // wait for all GEMM partials
    const int idx = blockIdx.x * 256 + threadIdx.x;   // b*HW + j
    float m = -INFINITY;
#pragma unroll 8
    for (int s = 0; s < NSPLIT; s++)
        m = fmaxf(m, g_pm[(size_t)s * BATCH * HW + idx]);
    float sum = 0.f;
#pragma unroll 8
    for (int s = 0; s < NSPLIT; s++)
        sum += g_ps[(size_t)s * BATCH * HW + idx] *
               __expf(g_pm[(size_t)s * BATCH * HW + idx] - m);
    const float inv = 1.f / sum;
#pragma unroll 8
    for (int s = 0; s < NSPLIT; s++)
        g_sc[(size_t)s * BATCH * HW + idx] =
            __expf(g_pm[(size_t)s * BATCH * HW + idx] - m) * inv;
}

// ------------------------------------------------------------------ finalize
__global__ __launch_bounds__(256) void finalize(float* __restrict__ out)
{
    cudaGridDependencySynchronize();     // wait for merge's g_sc
    const size_t q = ((size_t)blockIdx.x * 256 + threadIdx.x) * 8;
    const int j = (int)(q & (HW - 1));
    const int i = (int)((q >> 12) & (HW - 1));
    const int b = (int)(q >> 24);

    const uint4 eraw = *(const uint4*)(g_e + q);
    const float* sc = g_sc + (size_t)(i >> 6) * BATCH * HW + (size_t)b * HW + j;
    const float4 s0 = *(const float4*)(sc);
    const float4 s1 = *(const float4*)(sc + 4);

    const float2 p0 = __half22float2(*(const __half2*)&eraw.x);
    const float2 p1 = __half22float2(*(const __half2*)&eraw.y);
    const float2 p2 = __half22float2(*(const __half2*)&eraw.z);
    const float2 p3 = __half22float2(*(const __half2*)&eraw.w);

    float4 o0, o1;
    o0.x = p0.x * s0.x;  o0.y = p0.y * s0.y;
    o0.z = p1.x * s0.z;  o0.w = p1.y * s0.w;
    o1.x = p2.x * s1.x;  o1.y = p2.y * s1.y;
    o1.z = p3.x * s1.z;  o1.w = p3.y * s1.w;

    *(float4*)(out + q)     = o0;
    *(float4*)(out + q + 4) = o1;
}

// ------------------------------------------------------------------
extern "C" void kernel_launch(void* const* d_in, const int* in_sizes, int n_in,
                              void* d_out, int out_size)
{
    const float* f1 = (const float*)d_in[0];
    const float* f2 = (const float*)d_in[1];
    float* out = (float*)d_out;

    static bool smem_set = false;
    if (!smem_set) {
        cudaFuncSetAttribute(corr_mma, cudaFuncAttributeMaxDynamicSharedMemorySize, SMEM_REQ);
        smem_set = true;
    }

    split_prep<<<2048, 256>>>(f1, f2);

    cudaLaunchAttribute pdl;
    pdl.id = cudaLaunchAttributeProgrammaticStreamSerialization;
    pdl.val.programmaticStreamSerializationAllowed = 1;

    {   // GEMM with PDL (prologue overlaps prep tail)
        cudaLaunchConfig_t cfg = {};
        cfg.gridDim = dim3(HW / 128, HW / 128, BATCH);   // 32 x 32 x 4
        cfg.blockDim = dim3(128, 1, 1);
        cfg.dynamicSmemBytes = SMEM_REQ;
        cfg.attrs = &pdl;
        cfg.numAttrs = 1;
        cudaLaunchKernelEx(&cfg, corr_mma);
    }
    {   // merge with PDL (launch overlaps GEMM tail)
        cudaLaunchConfig_t cfg = {};
        cfg.gridDim = dim3((BATCH * HW) / 256, 1, 1);
        cfg.blockDim = dim3(256, 1, 1);
        cfg.attrs = &pdl;
        cfg.numAttrs = 1;
        cudaLaunchKernelEx(&cfg, merge_stats);
    }
    {   // finalize with PDL (launch overlaps merge)
        const size_t total = (size_t)BATCH * HW * HW;
        cudaLaunchConfig_t cfg = {};
        cfg.gridDim = dim3((unsigned)(total / 8 / 256), 1, 1);
        cfg.blockDim = dim3(256, 1, 1);
        cfg.attrs = &pdl;
        cfg.numAttrs = 1;
        cudaLaunchKernelEx(&cfg, finalize, out);
    }
}